// round 15
// baseline (speedup 1.0000x reference)
#include <cuda_runtime.h>
#include <cuda_bf16.h>
#include <cuda_fp16.h>
#include <stdint.h>

#define BB 4
#define SEQ 4096
#define DM 1024
#define DK 64
#define MTOT (BB*SEQ)
#define NSPLIT 2
#define TPS (SEQ/64/NSPLIT)

#define RSTRIDE_B 144
#define TILE_B    9216

// ---------------------------------------------------------------------------
// Scratch (device globals — allocation-free)
// ---------------------------------------------------------------------------
__device__ alignas(16) uint16_t g_qh_hi[MTOT*DK];
__device__ alignas(16) uint16_t g_qh_lo[MTOT*DK];
__device__ alignas(16) uint16_t g_kh_hi[MTOT*DK];
__device__ alignas(16) uint16_t g_kh_lo[MTOT*DK];
__device__ alignas(16) uint16_t g_vh[MTOT*DK];           // fp16 single
__device__ alignas(16) __nv_bfloat16 g_wh[4*64*1024];
__device__ alignas(16) __nv_bfloat16 g_wl[4*64*1024];
__device__ alignas(16) float g_part[NSPLIT*MTOT*DK];
__device__ alignas(8)  float2 g_ml[NSPLIT*MTOT];
__device__ uint32_t g_mpack[SEQ*SEQ/32];

// ---------------------------------------------------------------------------
// helpers
// ---------------------------------------------------------------------------
__device__ __forceinline__ uint32_t smem_u32(const void* p) {
    uint32_t a;
    asm("{ .reg .u64 t; cvta.to.shared.u64 t, %1; cvt.u32.u64 %0, t; }"
        : "=r"(a) : "l"(p));
    return a;
}
__device__ __forceinline__ void split2_pack(float v0, float v1,
                                            uint32_t& ph, uint32_t& pl) {
    uint32_t u0 = __float_as_uint(v0), u1 = __float_as_uint(v1);
    float h0 = __uint_as_float(u0 & 0xFFFF0000u);
    float h1 = __uint_as_float(u1 & 0xFFFF0000u);
    ph = __byte_perm(u0, u1, 0x7632);
    pl = __byte_perm(__float_as_uint(v0 - h0), __float_as_uint(v1 - h1), 0x7632);
}
#define CVT_F16X2(d, vhi, vlo) \
    asm("cvt.rn.f16x2.f32 %0, %1, %2;" : "=r"(d) : "f"(vhi), "f"(vlo))
__device__ __forceinline__ void split2_pack_f16(float v0, float v1,
                                                uint32_t& ph, uint32_t& pl) {
    __half h0 = __float2half_rn(v0), h1 = __float2half_rn(v1);
    __half2 H = __halves2half2(h0, h1);
    ph = *reinterpret_cast<uint32_t*>(&H);
    CVT_F16X2(pl, v1 - __half2float(h1), v0 - __half2float(h0));
}

#define LDSM_X4(r0,r1,r2,r3,addr) \
    asm volatile("ldmatrix.sync.aligned.m8n8.x4.shared.b16 {%0,%1,%2,%3}, [%4];" \
        : "=r"(r0), "=r"(r1), "=r"(r2), "=r"(r3) : "r"(addr))

#define LDSM_X4_T(r0,r1,r2,r3,addr) \
    asm volatile("ldmatrix.sync.aligned.m8n8.x4.trans.shared.b16 {%0,%1,%2,%3}, [%4];" \
        : "=r"(r0), "=r"(r1), "=r"(r2), "=r"(r3) : "r"(addr))

#define MMA16816(c, a0,a1,a2,a3, b0,b1) \
    asm volatile("mma.sync.aligned.m16n8k16.row.col.f32.bf16.bf16.f32 " \
        "{%0,%1,%2,%3},{%4,%5,%6,%7},{%8,%9},{%0,%1,%2,%3};" \
        : "+f"((c)[0]), "+f"((c)[1]), "+f"((c)[2]), "+f"((c)[3]) \
        : "r"(a0), "r"(a1), "r"(a2), "r"(a3), "r"(b0), "r"(b1))

#define MMA16816H(c, a0,a1,a2,a3, b0,b1) \
    asm volatile("mma.sync.aligned.m16n8k16.row.col.f32.f16.f16.f32 " \
        "{%0,%1,%2,%3},{%4,%5,%6,%7},{%8,%9},{%0,%1,%2,%3};" \
        : "+f"((c)[0]), "+f"((c)[1]), "+f"((c)[2]), "+f"((c)[3]) \
        : "r"(a0), "r"(a1), "r"(a2), "r"(a3), "r"(b0), "r"(b1))

#define CP16(dst_u32, src_ptr) \
    asm volatile("cp.async.cg.shared.global [%0], [%1], 16;" \
        :: "r"(dst_u32), "l"(src_ptr) : "memory")
#define CP_COMMIT() asm volatile("cp.async.commit_group;" ::: "memory")
#define CP_WAIT(N)  asm volatile("cp.async.wait_group %0;" :: "n"(N) : "memory")

// ---------------------------------------------------------------------------
// mask bit-pack (int4 vectorized)
// ---------------------------------------------------------------------------
__global__ __launch_bounds__(256) void pack_mask_kernel(const int* __restrict__ m)
{
    int t = blockIdx.x * 256 + threadIdx.x;
    int lane = threadIdx.x & 31;
    int4 mv = ((const int4*)m)[t];
    uint32_t nib = (mv.x != 0 ? 1u : 0u) | (mv.y != 0 ? 2u : 0u)
                 | (mv.z != 0 ? 4u : 0u) | (mv.w != 0 ? 8u : 0u);
    uint32_t v = nib << (4*(lane & 7));
    v |= __shfl_xor_sync(0xffffffffu, v, 1);
    v |= __shfl_xor_sync(0xffffffffu, v, 2);
    v |= __shfl_xor_sync(0xffffffffu, v, 4);
    if ((lane & 7) == 0) g_mpack[t >> 3] = v;
}

// ---------------------------------------------------------------------------
// weight split (bf16 trunc). z: 0=Wq 1=Wk 2=Wv 3=Wo
// ---------------------------------------------------------------------------
__global__ __launch_bounds__(256) void split_w_kernel(
    const float* __restrict__ Wq, const float* __restrict__ Wk,
    const float* __restrict__ Wv, const float* __restrict__ Wo)
{
    int z = blockIdx.y;
    const float* W = (z == 0) ? Wq : (z == 1) ? Wk : (z == 2) ? Wv : Wo;
    int i4 = blockIdx.x * 256 + threadIdx.x;
    float4 wv = ((const float4*)W)[i4];
    uint2 uh, ul;
    split2_pack(wv.x, wv.y, uh.x, ul.x);
    split2_pack(wv.z, wv.w, uh.y, ul.y);
    ((uint2*)(g_wh + (size_t)z*65536))[i4] = uh;
    ((uint2*)(g_wl + (size_t)z*65536))[i4] = ul;
}

// ---------------------------------------------------------------------------
// Q/K/V projection (bf16x3 internally). Epilogue: Q/K -> fp16 hi/lo (rn),
// V -> fp16 single (rn). CTA: 64 rows, 128 threads; grid (MTOT/64, 3).
// ---------------------------------------------------------------------------
__global__ __launch_bounds__(128, 3) void proj_mma_kernel(
    const float* __restrict__ q, const float* __restrict__ k, const float* __restrict__ v,
    const float* __restrict__ bq, const float* __restrict__ bk, const float* __restrict__ bv)
{
    extern __shared__ char psm[];
    const uint32_t sb = smem_u32(psm);
    const uint32_t oXh = 0, oXl = TILE_B;

    const int tid = threadIdx.x;
    const int w = tid >> 5, l = tid & 31;
    const int z = blockIdx.y;
    const int row0 = blockIdx.x * 64;

    const float* x    = (z == 0) ? q  : (z == 1) ? k  : v;
    const float* bias = (z == 0) ? bq : (z == 1) ? bk : bv;
    const __nv_bfloat16* gwh = g_wh + (size_t)z*65536;
    const __nv_bfloat16* gwl = g_wl + (size_t)z*65536;
    const float presc = (z == 0) ? 0.125f*1.44269504f : 1.0f;

    const int arow  = w*16 + (l & 7) + ((l >> 3) & 1)*8;
    const int acolb = ((l >> 3) & 2)*8;
    const int brow  = (l & 7) + ((l >> 3) & 2)*4;
    const int bcolb = ((l >> 3) & 1)*16;

    const int xr_r = tid >> 4;
    const int xr_c = tid & 15;

    float C[8][4];
    #pragma unroll
    for (int j = 0; j < 8; j++)
        #pragma unroll
        for (int i = 0; i < 4; i++) C[j][i] = 0.f;

    {
        #pragma unroll
        for (int it = 0; it < 4; it++) {
            int i = tid + it*128;
            int r = i >> 3, c = i & 7;
            uint32_t d = r*RSTRIDE_B + c*16;
            CP16(sb + 2*TILE_B + d, ((const uint4*)(gwh + (size_t)r*DM)) + c);
            CP16(sb + 3*TILE_B + d, ((const uint4*)(gwl + (size_t)r*DM)) + c);
        }
        CP_COMMIT();
    }
    float4 xr[8];
    #pragma unroll
    for (int it = 0; it < 8; it++) {
        int r = xr_r + it*8;
        xr[it] = *(const float4*)(x + (size_t)(row0 + r)*DM + xr_c*4);
    }

    for (int k0 = 0; k0 < DM; k0 += 64) {
        int kc = k0 >> 6;
        #pragma unroll
        for (int it = 0; it < 8; it++) {
            int r = xr_r + it*8;
            uint2 uh, ul;
            split2_pack(xr[it].x, xr[it].y, uh.x, ul.x);
            split2_pack(xr[it].z, xr[it].w, uh.y, ul.y);
            *(uint2*)(psm + oXh + r*RSTRIDE_B + xr_c*8) = uh;
            *(uint2*)(psm + oXl + r*RSTRIDE_B + xr_c*8) = ul;
        }
        if (k0 + 64 < DM) {
            #pragma unroll
            for (int it = 0; it < 8; it++) {
                int r = xr_r + it*8;
                xr[it] = *(const float4*)(x + (size_t)(row0 + r)*DM + k0 + 64 + xr_c*4);
            }
            uint32_t wb = sb + 2*TILE_B + ((kc+1)&1)*2*TILE_B;
            #pragma unroll
            for (int it = 0; it < 4; it++) {
                int i = tid + it*128;
                int r = i >> 3, c = i & 7;
                uint32_t d = r*RSTRIDE_B + c*16;
                CP16(wb + d,          ((const uint4*)(gwh + (size_t)r*DM + k0 + 64)) + c);
                CP16(wb + TILE_B + d, ((const uint4*)(gwl + (size_t)r*DM + k0 + 64)) + c);
            }
            CP_COMMIT();
            CP_WAIT(1);
        } else {
            CP_WAIT(0);
        }
        __syncthreads();

        const uint32_t aWh = sb + 2*TILE_B + (kc&1)*2*TILE_B;
        #pragma unroll
        for (int t = 0; t < 4; t++) {
            uint32_t ah[4], al[4];
            uint32_t aa = sb + oXh + arow*RSTRIDE_B + t*32 + acolb;
            LDSM_X4(ah[0], ah[1], ah[2], ah[3], aa);
            LDSM_X4(al[0], al[1], al[2], al[3], aa + TILE_B);
            #pragma unroll
            for (int g = 0; g < 4; g++) {
                uint32_t ba = aWh + (g*16 + brow)*RSTRIDE_B + t*32 + bcolb;
                uint32_t h0,h1,h2,h3, w0,w1,w2,w3;
                LDSM_X4(h0,h1,h2,h3, ba);
                LDSM_X4(w0,w1,w2,w3, ba + TILE_B);
                MMA16816(C[2*g],   ah[0],ah[1],ah[2],ah[3], h0,h1);
                MMA16816(C[2*g],   ah[0],ah[1],ah[2],ah[3], w0,w1);
                MMA16816(C[2*g],   al[0],al[1],al[2],al[3], h0,h1);
                MMA16816(C[2*g+1], ah[0],ah[1],ah[2],ah[3], h2,h3);
                MMA16816(C[2*g+1], ah[0],ah[1],ah[2],ah[3], w2,w3);
                MMA16816(C[2*g+1], al[0],al[1],al[2],al[3], h2,h3);
            }
        }
        __syncthreads();
    }

    const int row_lo = row0 + w*16 + (l >> 2);
    const int row_hi = row_lo + 8;
    if (z < 2) {
        uint16_t* yh = (z == 0) ? g_qh_hi : g_kh_hi;
        uint16_t* yl = (z == 0) ? g_qh_lo : g_kh_lo;
        uint32_t* yh0 = (uint32_t*)(yh + (size_t)row_lo*DK);
        uint32_t* yl0 = (uint32_t*)(yl + (size_t)row_lo*DK);
        uint32_t* yh1 = (uint32_t*)(yh + (size_t)row_hi*DK);
        uint32_t* yl1 = (uint32_t*)(yl + (size_t)row_hi*DK);
        #pragma unroll
        for (int j = 0; j < 8; j++) {
            int c = j*8 + 2*(l & 3);
            float b0 = bias[c], b1 = bias[c+1];
            uint32_t uh, ul;
            split2_pack_f16((C[j][0] + b0)*presc, (C[j][1] + b1)*presc, uh, ul);
            yh0[j*4 + (l & 3)] = uh;
            yl0[j*4 + (l & 3)] = ul;
            split2_pack_f16((C[j][2] + b0)*presc, (C[j][3] + b1)*presc, uh, ul);
            yh1[j*4 + (l & 3)] = uh;
            yl1[j*4 + (l & 3)] = ul;
        }
    } else {
        uint32_t* y0 = (uint32_t*)(g_vh + (size_t)row_lo*DK);
        uint32_t* y1 = (uint32_t*)(g_vh + (size_t)row_hi*DK);
        #pragma unroll
        for (int j = 0; j < 8; j++) {
            int c = j*8 + 2*(l & 3);
            float b0 = bias[c], b1 = bias[c+1];
            uint32_t u;
            CVT_F16X2(u, C[j][1] + b1, C[j][0] + b0);
            y0[j*4 + (l & 3)] = u;
            CVT_F16X2(u, C[j][3] + b1, C[j][2] + b0);
            y1[j*4 + (l & 3)] = u;
        }
    }
}

// ---------------------------------------------------------------------------
// Flash attention split-K (fp16 QK 3-term, PV 1-term; log2 units).
// CTA = 64 q x 128 thr, 3 CTA/SM. dyn smem 55296:
// Qh 0, Ql T, Kh 2T, Kl 3T, V0 4T, V1 5T. (R13 structure; mask loads hoisted)
// ---------------------------------------------------------------------------
__global__ __launch_bounds__(128, 3) void attn_mma_kernel()
{
    extern __shared__ char sbuf[];
    const uint32_t sbase = smem_u32(sbuf);
    const uint32_t oQh = 0, oQl = TILE_B;
    const uint32_t oKh = 2*TILE_B, oKl = 3*TILE_B;

    const int tid = threadIdx.x;
    const int w   = tid >> 5;
    const int l   = tid & 31;
    const int b   = blockIdx.y;
    const int q0  = blockIdx.x * 64;
    const int sp  = blockIdx.z;
    const int t0  = sp * TPS;

    const uint4* gkh = (const uint4*)(g_kh_hi + (size_t)b*SEQ*DK);
    const uint4* gkl = (const uint4*)(g_kh_lo + (size_t)b*SEQ*DK);
    const uint4* gv  = (const uint4*)(g_vh   + (size_t)b*SEQ*DK);

    {
        const uint4* gqh = (const uint4*)(g_qh_hi + (size_t)(b*SEQ + q0)*DK);
        const uint4* gql = (const uint4*)(g_qh_lo + (size_t)(b*SEQ + q0)*DK);
        int k0 = t0*64;
        #pragma unroll
        for (int it = 0; it < 4; it++) {
            int i = tid + it*128;
            int r = i >> 3, c = i & 7;
            uint32_t d = r*RSTRIDE_B + c*16;
            size_t gi = (size_t)(k0 + r)*8 + c;
            CP16(sbase + oQh + d, gqh + i);
            CP16(sbase + oQl + d, gql + i);
            CP16(sbase + oKh + d, gkh + gi);
            CP16(sbase + oKl + d, gkl + gi);
            CP16(sbase + 4*TILE_B + d, gv + gi);
        }
        CP_COMMIT();
        CP_WAIT(0);
    }
    __syncthreads();

    const int arow     = w*16 + (l & 7) + ((l >> 3) & 1)*8;
    const int acolb    = ((l >> 3) & 2)*8;
    const int brow_off = (l & 7) + ((l >> 3) & 2)*4;
    const int bcol_off = ((l >> 3) & 1)*16;
    const int vrow_off = (l & 7) + ((l >> 3) & 1)*8;
    const int vcol_off = ((l >> 4) & 1)*16;

    float O[8][4];
    #pragma unroll
    for (int j = 0; j < 8; j++)
        #pragma unroll
        for (int i = 0; i < 4; i++) O[j][i] = 0.f;
    float mr[2] = {-1e30f, -1e30f};
    float lr[2] = {0.f, 0.f};

    const int q_lo = q0 + w*16 + (l >> 2);
    const int q_hi = q_lo + 8;

    for (int ti = t0; ti < t0 + TPS; ti++) {
        const int k0 = ti*64;
        const bool more = (ti + 1 < t0 + TPS);
        const uint32_t oV = sbase + (4u + (uint32_t)(ti & 1))*TILE_B;

        // hoisted mask loads — land during QK MMA phase
        uint2 m0 = *(const uint2*)(g_mpack + (size_t)q_lo*(SEQ/32) + (k0 >> 5));
        uint2 m1 = *(const uint2*)(g_mpack + (size_t)q_hi*(SEQ/32) + (k0 >> 5));

        // ---- S = Q K^T (fp16 3-term) ----
        float S[8][4];
        #pragma unroll
        for (int j = 0; j < 8; j++)
            #pragma unroll
            for (int i = 0; i < 4; i++) S[j][i] = 0.f;

        #pragma unroll
        for (int t = 0; t < 4; t++) {
            uint32_t qh0,qh1,qh2,qh3, ql0,ql1,ql2,ql3;
            uint32_t qa = sbase + oQh + arow*RSTRIDE_B + t*32 + acolb;
            LDSM_X4(qh0,qh1,qh2,qh3, qa);
            LDSM_X4(ql0,ql1,ql2,ql3, qa + TILE_B);
            #pragma unroll
            for (int g = 0; g < 4; g++) {
                uint32_t a = sbase + oKh + (g*16 + brow_off)*RSTRIDE_B + t*32 + bcol_off;
                uint32_t h0,h1,h2,h3, l0,l1,l2,l3;
                LDSM_X4(h0,h1,h2,h3, a);
                LDSM_X4(l0,l1,l2,l3, a + TILE_B);
                MMA16816H(S[2*g],   qh0,qh1,qh2,qh3, h0,h1);
                MMA16816H(S[2*g],   qh0,qh1,qh2,qh3, l0,l1);
                MMA16816H(S[2*g],   ql0,ql1,ql2,ql3, h0,h1);
                MMA16816H(S[2*g+1], qh0,qh1,qh2,qh3, h2,h3);
                MMA16816H(S[2*g+1], qh0,qh1,qh2,qh3, l2,l3);
                MMA16816H(S[2*g+1], ql0,ql1,ql2,ql3, h2,h3);
            }
        }
        __syncthreads();   // K reads complete CTA-wide; PV(ti-1) done by all warps

        // prefetch K(ti+1) and V(ti+1) — land behind softmax + PV
        if (more) {
            uint32_t nV = sbase + (4u + (uint32_t)((ti+1) & 1))*TILE_B;
            #pragma unroll
            for (int it = 0; it < 4; it++) {
                int i = tid + it*128;
                int r = i >> 3, c = i & 7;
                uint32_t d = r*RSTRIDE_B + c*16;
                size_t gi = (size_t)(k0 + 64 + r)*8 + c;
                CP16(sbase + oKh + d, gkh + gi);
                CP16(sbase + oKl + d, gkl + gi);
                CP16(nV + d,          gv  + gi);
            }
            CP_COMMIT();
        }

        // ---- mask ----
        {
            uint64_t w0 = ((uint64_t)m0.y << 32) | m0.x;
            uint64_t w1 = ((uint64_t)m1.y << 32) | m1.x;
            #pragma unroll
            for (int j = 0; j < 8; j++) {
                int c = j*8 + 2*(l & 3);
                if (!((w0 >> c) & 1))     S[j][0] = -1e9f;
                if (!((w0 >> (c+1)) & 1)) S[j][1] = -1e9f;
                if (!((w1 >> c) & 1))     S[j][2] = -1e9f;
                if (!((w1 >> (c+1)) & 1)) S[j][3] = -1e9f;
            }
        }

        // ---- online softmax (base-2) ----
        float mx0 = -1e30f, mx1 = -1e30f;
        #pragma unroll
        for (int j = 0; j < 8; j++) {
            mx0 = fmaxf(mx0, fmaxf(S[j][0], S[j][1]));
            mx1 = fmaxf(mx1, fmaxf(S[j][2], S[j][3]));
        }
        mx0 = fmaxf(mx0, __shfl_xor_sync(0xffffffffu, mx0, 1));
        mx0 = fmaxf(mx0, __shfl_xor_sync(0xffffffffu, mx0, 2));
        mx1 = fmaxf(mx1, __shfl_xor_sync(0xffffffffu, mx1, 1));
        mx1 = fmaxf(mx1, __shfl_xor_sync(0xffffffffu, mx1, 2));
        float mn0 = fmaxf(mr[0], mx0), mn1 = fmaxf(mr[1], mx1);
        float cr0 = exp2f(mr[0] - mn0), cr1 = exp2f(mr[1] - mn1);
        mr[0] = mn0; mr[1] = mn1;

        float ps0 = 0.f, ps1 = 0.f;
        uint32_t pa[4][4];
        #pragma unroll
        for (int t = 0; t < 4; t++) {
            float p[8];
            #pragma unroll
            for (int u = 0; u < 2; u++) {
                int j = 2*t + u;
                p[4*u+0] = exp2f(S[j][0] - mn0);
                p[4*u+1] = exp2f(S[j][1] - mn0);
                p[4*u+2] = exp2f(S[j][2] - mn1);
                p[4*u+3] = exp2f(S[j][3] - mn1);
                ps0 += p[4*u+0] + p[4*u+1];
                ps1 += p[4*u+2] + p[4*u+3];
            }
            CVT_F16X2(pa[t][0], p[1], p[0]);
            CVT_F16X2(pa[t][1], p[3], p[2]);
            CVT_F16X2(pa[t][2], p[5], p[4]);
            CVT_F16X2(pa[t][3], p[7], p[6]);
        }
        ps0 += __shfl_xor_sync(0xffffffffu, ps0, 1);
        ps0 += __shfl_xor_sync(0xffffffffu, ps0, 2);
        ps1 += __shfl_xor_sync(0xffffffffu, ps1, 1);
        ps1 += __shfl_xor_sync(0xffffffffu, ps1, 2);
        lr[0] = lr[0]*cr0 + ps0;
        lr[1] = lr[1]*cr1 + ps1;

        #pragma unroll
        for (int j = 0; j < 8; j++) {
            O[j][0] *= cr0; O[j][1] *= cr0;
            O[j][2] *= cr1; O[j][3] *= cr1;
        }

        // ---- O += P V (fp16 1-term) ----
        #pragma unroll
        for (int t = 0; t < 4; t++) {
            #pragma unroll
            for (int g = 0; g < 4; g++) {
                uint32_t a = oV + (t*16 + vrow_off)*RSTRIDE_B + g*32 + vcol_off;
                uint32_t h0,h1,h2,h3;
                LDSM_X4_T(h0,h1,h2,h3, a);
                MMA16816H(O[2*g],   pa[t][0],pa[t][1],pa[t][2],pa[t][3], h0,h1);
                MMA16816H(O[2*g+1], pa[t][0],pa[t][1],pa[t][2],pa[t][3], h2,h3);
            }
        }

        if (more) {
            CP_WAIT(0);
            __syncthreads();
        }
    }

    // ---- write unnormalized partials + (m, l) ----
    {
        float* po0 = g_part + ((size_t)sp*MTOT + b*SEQ + q_lo)*DK;
        float* po1 = g_part + ((size_t)sp*MTOT + b*SEQ + q_hi)*DK;
        #pragma unroll
        for (int j = 0; j < 8; j++) {
            int c = j*8 + 2*(l & 3);
            float2 v0 = { O[j][0], O[j][1] };
            float2 v1 = { O[j][2], O[j][3] };
            *(float2*)(po0 + c) = v0;
            *(float2*)(po1 + c) = v1;
        }
        if ((l & 3) == 0) {
            g_ml[(size_t)sp*MTOT + b*SEQ + q_lo] = make_float2(mr[0], lr[0]);
            g_ml[(size_t)sp*MTOT + b*SEQ + q_hi] = make_float2(mr[1], lr[1]);
        }
    }
}

// ---------------------------------------------------------------------------
// Output projection + inline split-K merge.
// grid (MTOT/64, 2): y selects N-half (8 chunks of 64). CTA: 64 rows, 128 thr.
// dyn smem 55296: Ah 0, Al T, Wbuf0 {2T,3T}, Wbuf1 {4T,5T}.
// ---------------------------------------------------------------------------
__global__ __launch_bounds__(128, 3) void oproj_mma_kernel(
    const float* __restrict__ bo, float* __restrict__ out)
{
    extern __shared__ char psm[];
    const uint32_t sb = smem_u32(psm);

    const int tid = threadIdx.x;
    const int w = tid >> 5, l = tid & 31;
    const int row0 = blockIdx.x * 64;
    const int nh   = blockIdx.y;            // N half: chunks nh*8 .. nh*8+7

    const __nv_bfloat16* gwh = g_wh + (size_t)3*65536;
    const __nv_bfloat16* gwl = g_wl + (size_t)3*65536;

    // Wo chunk (nh*8) via cp.async while we merge-stage A
    {
        int n0 = nh*512;
        #pragma unroll
        for (int it = 0; it < 4; it++) {
            int i = tid + it*128;
            int r = i >> 3, c = i & 7;
            uint32_t d = r*RSTRIDE_B + c*16;
            CP16(sb + 2*TILE_B + d, ((const uint4*)(gwh + (size_t)(n0 + r)*DK)) + c);
            CP16(sb + 3*TILE_B + d, ((const uint4*)(gwl + (size_t)(n0 + r)*DK)) + c);
        }
        CP_COMMIT();
    }

    // inline split-K merge: stage A = normalize+combine partials -> bf16 hi/lo smem
    #pragma unroll
    for (int it = 0; it < 8; it++) {
        int i = tid + it*128;                // 0..1023: 64 rows x 16 col-pairs
        int r = i >> 4, cp = i & 15;         // cp: 4-float group
        int row = row0 + r;
        float2 ml0 = g_ml[row];
        float2 ml1 = g_ml[MTOT + row];
        float M = fmaxf(ml0.x, ml1.x);
        float a0 = exp2f(ml0.x - M);
        float a1 = exp2f(ml1.x - M);
        float inv = 1.f / (ml0.y*a0 + ml1.y*a1);
        float4 o0 = *(const float4*)(g_part + (size_t)row*DK + cp*4);
        float4 o1 = *(const float4*)(g_part + ((size_t)MTOT + row)*DK + cp*4);
        uint2 uh, ul;
        split2_pack((o0.x*a0 + o1.x*a1)*inv, (o0.y*a0 + o1.y*a1)*inv, uh.x, ul.x);
        split2_pack((o0.z*a0 + o1.z*a1)*inv, (o0.w*a0 + o1.w*a1)*inv, uh.y, ul.y);
        *(uint2*)(psm + r*RSTRIDE_B + cp*8) = uh;
        *(uint2*)(psm + TILE_B + r*RSTRIDE_B + cp*8) = ul;
    }
    CP_WAIT(0);
    __syncthreads();

    uint32_t oa_h[4][4], oa_l[4][4];
    {
        int row = w*16 + (l & 7) + ((l >> 3) & 1)*8;
        int colb_off = ((l >> 3) & 2)*8;
        #pragma unroll
        for (int t = 0; t < 4; t++) {
            uint32_t a = sb + row*RSTRIDE_B + t*32 + colb_off;
            LDSM_X4(oa_h[t][0], oa_h[t][1], oa_h[t][2], oa_h[t][3], a);
            LDSM_X4(oa_l[t][0], oa_l[t][1], oa_l[t][2], oa_l[t][3], a + TILE_B);
        }
    }

    const int brow  = (l & 7) + ((l >> 3) & 2)*4;
    const int bcolb = ((l >> 3) & 1)*16;
    const int row_lo = row0 + w*16 + (l >> 2);
    const int row_hi = row_lo + 8;

    for (int nc = 0; nc < 8; nc++) {
        const int n0 = nh*512 + nc*64;
        if (nc + 1 < 8) {
            uint32_t wb = sb + 2*TILE_B + ((nc+1)&1)*2*TILE_B;
            #pragma unroll
            for (int it = 0; it < 4; it++) {
                int i = tid + it*128;
                int r = i >> 3, c = i & 7;
                uint32_t d = r*RSTRIDE_B + c*16;
                CP16(wb + d,          ((const uint4*)(gwh + (size_t)(n0 + 64 + r)*DK)) + c);
                CP16(wb + TILE_B + d, ((const uint4*)(gwl + (size_t)(n0 + 64 + r)*DK)) + c);
            }
            CP_COMMIT();
            CP_WAIT(1);
        } else {
            CP_WAIT(0);
        }
        __syncthreads();

        const uint32_t aWh = sb + 2*TILE_B + (nc&1)*2*TILE_B;
        float C[8][4];
        #pragma unroll
        for (int j = 0; j < 8; j++)
            #pragma unroll
            for (int i = 0; i < 4; i++) C[j][i] = 0.f;

        #pragma unroll
        for (int t = 0; t < 4; t++) {
            #pragma unroll
            for (int g = 0; g < 4; g++) {
                uint32_t ba = aWh + (g*16 + brow)*RSTRIDE_B + t*32 + bcolb;
                uint32_t h0,h1,h2,h3, w0,w1,w2,w3;
                LDSM_X4(h0,h1,h2,h3, ba);
                LDSM_X4(w0,w1,w2,w3, ba + TILE_B);
                MMA16816(C[2*g],   oa_h[t][0],oa_h[t][1],oa_h[t][2],oa_h[t][3], h0,h1);
                MMA16816(C[2*g],   oa_h[t][0],oa_h[t][1],oa_h[t][2],oa_h[t][3], w0,w1);
                MMA16816(C[2*g],   oa_l[t][0],oa_l[t][1],oa_l[t][2],oa_l[t][3], h0,h1);
                MMA16816(C[2*g+1], oa_h[t][0],oa_h[t][1],oa_h[t][2],oa_h[t][3], h2,h3);
                MMA16816(C[2*g+1], oa_h[t][0],oa_h[t][1],oa_h[t][2],oa_h[t][3], w2,w3);
                MMA16816(C[2*g+1], oa_l[t][0],oa_l[t][1],oa_l[t][2],oa_l[t][3], h2,h3);
            }
        }

        float2* po0 = (float2*)(out + (size_t)row_lo*DM + n0);
        float2* po1 = (float2*)(out + (size_t)row_hi*DM + n0);
        #pragma unroll
        for (int j = 0; j < 8; j++) {
            int c = j*8 + 2*(l & 3);
            float b0v = bo[n0 + c], b1v = bo[n0 + c + 1];
            float2 v0 = { C[j][0] + b0v, C[j][1] + b1v };
            float2 v1 = { C[j][2] + b0v, C[j][3] + b1v };
            po0[j*4 + (l & 3)] = v0;
            po1[j*4 + (l & 3)] = v1;
        }
        __syncthreads();
    }
}

// ---------------------------------------------------------------------------
extern "C" void kernel_launch(void* const* d_in, const int* in_sizes, int n_in,
                              void* d_out, int out_size)
{
    const float* q    = (const float*)d_in[0];
    const float* k    = (const float*)d_in[1];
    const float* v    = (const float*)d_in[2];
    const int*   mask = (const int*)  d_in[3];
    const float* Wq   = (const float*)d_in[4];
    const float* bq   = (const float*)d_in[5];
    const float* Wk   = (const float*)d_in[6];
    const float* bk   = (const float*)d_in[7];
    const float* Wv   = (const float*)d_in[8];
    const float* bv   = (const float*)d_in[9];
    const float* Wo   = (const float*)d_in[10];
    const float* bo   = (const float*)d_in[11];
    float* out = (float*)d_out;

    const int smem6 = 6*TILE_B;    // 55296
    cudaFuncSetAttribute(proj_mma_kernel,
                         cudaFuncAttributeMaxDynamicSharedMemorySize, smem6);
    cudaFuncSetAttribute(attn_mma_kernel,
                         cudaFuncAttributeMaxDynamicSharedMemorySize, smem6);
    cudaFuncSetAttribute(oproj_mma_kernel,
                         cudaFuncAttributeMaxDynamicSharedMemorySize, smem6);

    pack_mask_kernel<<<SEQ*SEQ/4/256, 256>>>(mask);
    split_w_kernel<<<dim3(64, 4), 256>>>(Wq, Wk, Wv, Wo);

    proj_mma_kernel<<<dim3(MTOT/64, 3), 128, smem6>>>(q, k, v, bq, bk, bv);

    attn_mma_kernel<<<dim3(SEQ/64, BB, NSPLIT), 128, smem6>>>();

    oproj_mma_kernel<<<dim3(MTOT/64, 2), 128, smem6>>>(bo, out);
}

// round 16
// speedup vs baseline: 1.0360x; 1.0360x over previous
#include <cuda_runtime.h>
#include <cuda_bf16.h>
#include <cuda_fp16.h>
#include <stdint.h>

#define BB 4
#define SEQ 4096
#define DM 1024
#define DK 64
#define MTOT (BB*SEQ)
#define NSPLIT 2
#define TPS (SEQ/64/NSPLIT)

#define RSTRIDE_B 144
#define TILE_B    9216

// ---------------------------------------------------------------------------
// Scratch (device globals — allocation-free)
// ---------------------------------------------------------------------------
__device__ alignas(16) uint16_t g_qh_hi[MTOT*DK];
__device__ alignas(16) uint16_t g_qh_lo[MTOT*DK];
__device__ alignas(16) uint16_t g_kh_hi[MTOT*DK];
__device__ alignas(16) uint16_t g_kh_lo[MTOT*DK];
__device__ alignas(16) uint16_t g_vh[MTOT*DK];           // fp16 single
__device__ alignas(16) __nv_bfloat16 g_aoh[MTOT*DK];
__device__ alignas(16) __nv_bfloat16 g_aol[MTOT*DK];
__device__ alignas(16) __nv_bfloat16 g_wh[4*64*1024];
__device__ alignas(16) __nv_bfloat16 g_wl[4*64*1024];
__device__ alignas(16) float g_part[NSPLIT*MTOT*DK];
__device__ alignas(8)  float2 g_ml[NSPLIT*MTOT];
__device__ uint32_t g_mpack[SEQ*SEQ/32];

// ---------------------------------------------------------------------------
// helpers
// ---------------------------------------------------------------------------
__device__ __forceinline__ uint32_t smem_u32(const void* p) {
    uint32_t a;
    asm("{ .reg .u64 t; cvta.to.shared.u64 t, %1; cvt.u32.u64 %0, t; }"
        : "=r"(a) : "l"(p));
    return a;
}
__device__ __forceinline__ void split2_pack(float v0, float v1,
                                            uint32_t& ph, uint32_t& pl) {
    uint32_t u0 = __float_as_uint(v0), u1 = __float_as_uint(v1);
    float h0 = __uint_as_float(u0 & 0xFFFF0000u);
    float h1 = __uint_as_float(u1 & 0xFFFF0000u);
    ph = __byte_perm(u0, u1, 0x7632);
    pl = __byte_perm(__float_as_uint(v0 - h0), __float_as_uint(v1 - h1), 0x7632);
}
#define CVT_F16X2(d, vhi, vlo) \
    asm("cvt.rn.f16x2.f32 %0, %1, %2;" : "=r"(d) : "f"(vhi), "f"(vlo))
__device__ __forceinline__ void split2_pack_f16(float v0, float v1,
                                                uint32_t& ph, uint32_t& pl) {
    __half h0 = __float2half_rn(v0), h1 = __float2half_rn(v1);
    __half2 H = __halves2half2(h0, h1);
    ph = *reinterpret_cast<uint32_t*>(&H);
    CVT_F16X2(pl, v1 - __half2float(h1), v0 - __half2float(h0));
}

#define LDSM_X4(r0,r1,r2,r3,addr) \
    asm volatile("ldmatrix.sync.aligned.m8n8.x4.shared.b16 {%0,%1,%2,%3}, [%4];" \
        : "=r"(r0), "=r"(r1), "=r"(r2), "=r"(r3) : "r"(addr))

#define LDSM_X4_T(r0,r1,r2,r3,addr) \
    asm volatile("ldmatrix.sync.aligned.m8n8.x4.trans.shared.b16 {%0,%1,%2,%3}, [%4];" \
        : "=r"(r0), "=r"(r1), "=r"(r2), "=r"(r3) : "r"(addr))

#define MMA16816(c, a0,a1,a2,a3, b0,b1) \
    asm volatile("mma.sync.aligned.m16n8k16.row.col.f32.bf16.bf16.f32 " \
        "{%0,%1,%2,%3},{%4,%5,%6,%7},{%8,%9},{%0,%1,%2,%3};" \
        : "+f"((c)[0]), "+f"((c)[1]), "+f"((c)[2]), "+f"((c)[3]) \
        : "r"(a0), "r"(a1), "r"(a2), "r"(a3), "r"(b0), "r"(b1))

#define MMA16816H(c, a0,a1,a2,a3, b0,b1) \
    asm volatile("mma.sync.aligned.m16n8k16.row.col.f32.f16.f16.f32 " \
        "{%0,%1,%2,%3},{%4,%5,%6,%7},{%8,%9},{%0,%1,%2,%3};" \
        : "+f"((c)[0]), "+f"((c)[1]), "+f"((c)[2]), "+f"((c)[3]) \
        : "r"(a0), "r"(a1), "r"(a2), "r"(a3), "r"(b0), "r"(b1))

#define CP16(dst_u32, src_ptr) \
    asm volatile("cp.async.cg.shared.global [%0], [%1], 16;" \
        :: "r"(dst_u32), "l"(src_ptr) : "memory")
#define CP_COMMIT() asm volatile("cp.async.commit_group;" ::: "memory")
#define CP_WAIT(N)  asm volatile("cp.async.wait_group %0;" :: "n"(N) : "memory")

// ---------------------------------------------------------------------------
// mask bit-pack (int4 vectorized)
// ---------------------------------------------------------------------------
__global__ __launch_bounds__(256) void pack_mask_kernel(const int* __restrict__ m)
{
    int t = blockIdx.x * 256 + threadIdx.x;
    int lane = threadIdx.x & 31;
    int4 mv = ((const int4*)m)[t];
    uint32_t nib = (mv.x != 0 ? 1u : 0u) | (mv.y != 0 ? 2u : 0u)
                 | (mv.z != 0 ? 4u : 0u) | (mv.w != 0 ? 8u : 0u);
    uint32_t v = nib << (4*(lane & 7));
    v |= __shfl_xor_sync(0xffffffffu, v, 1);
    v |= __shfl_xor_sync(0xffffffffu, v, 2);
    v |= __shfl_xor_sync(0xffffffffu, v, 4);
    if ((lane & 7) == 0) g_mpack[t >> 3] = v;
}

// ---------------------------------------------------------------------------
// weight split (bf16 trunc). z: 0=Wq 1=Wk 2=Wv 3=Wo
// ---------------------------------------------------------------------------
__global__ __launch_bounds__(256) void split_w_kernel(
    const float* __restrict__ Wq, const float* __restrict__ Wk,
    const float* __restrict__ Wv, const float* __restrict__ Wo)
{
    int z = blockIdx.y;
    const float* W = (z == 0) ? Wq : (z == 1) ? Wk : (z == 2) ? Wv : Wo;
    int i4 = blockIdx.x * 256 + threadIdx.x;
    float4 wv = ((const float4*)W)[i4];
    uint2 uh, ul;
    split2_pack(wv.x, wv.y, uh.x, ul.x);
    split2_pack(wv.z, wv.w, uh.y, ul.y);
    ((uint2*)(g_wh + (size_t)z*65536))[i4] = uh;
    ((uint2*)(g_wl + (size_t)z*65536))[i4] = ul;
}

// ---------------------------------------------------------------------------
// Q/K/V projection (bf16x3 internally). Epilogue: Q/K -> fp16 hi/lo (rn),
// V -> fp16 single (rn). CTA: 64 rows, 128 threads; grid (MTOT/64, 3).
// (verbatim R13)
// ---------------------------------------------------------------------------
__global__ __launch_bounds__(128, 3) void proj_mma_kernel(
    const float* __restrict__ q, const float* __restrict__ k, const float* __restrict__ v,
    const float* __restrict__ bq, const float* __restrict__ bk, const float* __restrict__ bv)
{
    extern __shared__ char psm[];
    const uint32_t sb = smem_u32(psm);
    const uint32_t oXh = 0, oXl = TILE_B;

    const int tid = threadIdx.x;
    const int w = tid >> 5, l = tid & 31;
    const int z = blockIdx.y;
    const int row0 = blockIdx.x * 64;

    const float* x    = (z == 0) ? q  : (z == 1) ? k  : v;
    const float* bias = (z == 0) ? bq : (z == 1) ? bk : bv;
    const __nv_bfloat16* gwh = g_wh + (size_t)z*65536;
    const __nv_bfloat16* gwl = g_wl + (size_t)z*65536;
    const float presc = (z == 0) ? 0.125f*1.44269504f : 1.0f;

    const int arow  = w*16 + (l & 7) + ((l >> 3) & 1)*8;
    const int acolb = ((l >> 3) & 2)*8;
    const int brow  = (l & 7) + ((l >> 3) & 2)*4;
    const int bcolb = ((l >> 3) & 1)*16;

    const int xr_r = tid >> 4;
    const int xr_c = tid & 15;

    float C[8][4];
    #pragma unroll
    for (int j = 0; j < 8; j++)
        #pragma unroll
        for (int i = 0; i < 4; i++) C[j][i] = 0.f;

    {
        #pragma unroll
        for (int it = 0; it < 4; it++) {
            int i = tid + it*128;
            int r = i >> 3, c = i & 7;
            uint32_t d = r*RSTRIDE_B + c*16;
            CP16(sb + 2*TILE_B + d, ((const uint4*)(gwh + (size_t)r*DM)) + c);
            CP16(sb + 3*TILE_B + d, ((const uint4*)(gwl + (size_t)r*DM)) + c);
        }
        CP_COMMIT();
    }
    float4 xr[8];
    #pragma unroll
    for (int it = 0; it < 8; it++) {
        int r = xr_r + it*8;
        xr[it] = *(const float4*)(x + (size_t)(row0 + r)*DM + xr_c*4);
    }

    for (int k0 = 0; k0 < DM; k0 += 64) {
        int kc = k0 >> 6;
        #pragma unroll
        for (int it = 0; it < 8; it++) {
            int r = xr_r + it*8;
            uint2 uh, ul;
            split2_pack(xr[it].x, xr[it].y, uh.x, ul.x);
            split2_pack(xr[it].z, xr[it].w, uh.y, ul.y);
            *(uint2*)(psm + oXh + r*RSTRIDE_B + xr_c*8) = uh;
            *(uint2*)(psm + oXl + r*RSTRIDE_B + xr_c*8) = ul;
        }
        if (k0 + 64 < DM) {
            #pragma unroll
            for (int it = 0; it < 8; it++) {
                int r = xr_r + it*8;
                xr[it] = *(const float4*)(x + (size_t)(row0 + r)*DM + k0 + 64 + xr_c*4);
            }
            uint32_t wb = sb + 2*TILE_B + ((kc+1)&1)*2*TILE_B;
            #pragma unroll
            for (int it = 0; it < 4; it++) {
                int i = tid + it*128;
                int r = i >> 3, c = i & 7;
                uint32_t d = r*RSTRIDE_B + c*16;
                CP16(wb + d,          ((const uint4*)(gwh + (size_t)r*DM + k0 + 64)) + c);
                CP16(wb + TILE_B + d, ((const uint4*)(gwl + (size_t)r*DM + k0 + 64)) + c);
            }
            CP_COMMIT();
            CP_WAIT(1);
        } else {
            CP_WAIT(0);
        }
        __syncthreads();

        const uint32_t aWh = sb + 2*TILE_B + (kc&1)*2*TILE_B;
        #pragma unroll
        for (int t = 0; t < 4; t++) {
            uint32_t ah[4], al[4];
            uint32_t aa = sb + oXh + arow*RSTRIDE_B + t*32 + acolb;
            LDSM_X4(ah[0], ah[1], ah[2], ah[3], aa);
            LDSM_X4(al[0], al[1], al[2], al[3], aa + TILE_B);
            #pragma unroll
            for (int g = 0; g < 4; g++) {
                uint32_t ba = aWh + (g*16 + brow)*RSTRIDE_B + t*32 + bcolb;
                uint32_t h0,h1,h2,h3, w0,w1,w2,w3;
                LDSM_X4(h0,h1,h2,h3, ba);
                LDSM_X4(w0,w1,w2,w3, ba + TILE_B);
                MMA16816(C[2*g],   ah[0],ah[1],ah[2],ah[3], h0,h1);
                MMA16816(C[2*g],   ah[0],ah[1],ah[2],ah[3], w0,w1);
                MMA16816(C[2*g],   al[0],al[1],al[2],al[3], h0,h1);
                MMA16816(C[2*g+1], ah[0],ah[1],ah[2],ah[3], h2,h3);
                MMA16816(C[2*g+1], ah[0],ah[1],ah[2],ah[3], w2,w3);
                MMA16816(C[2*g+1], al[0],al[1],al[2],al[3], h2,h3);
            }
        }
        __syncthreads();
    }

    const int row_lo = row0 + w*16 + (l >> 2);
    const int row_hi = row_lo + 8;
    if (z < 2) {
        uint16_t* yh = (z == 0) ? g_qh_hi : g_kh_hi;
        uint16_t* yl = (z == 0) ? g_qh_lo : g_kh_lo;
        uint32_t* yh0 = (uint32_t*)(yh + (size_t)row_lo*DK);
        uint32_t* yl0 = (uint32_t*)(yl + (size_t)row_lo*DK);
        uint32_t* yh1 = (uint32_t*)(yh + (size_t)row_hi*DK);
        uint32_t* yl1 = (uint32_t*)(yl + (size_t)row_hi*DK);
        #pragma unroll
        for (int j = 0; j < 8; j++) {
            int c = j*8 + 2*(l & 3);
            float b0 = bias[c], b1 = bias[c+1];
            uint32_t uh, ul;
            split2_pack_f16((C[j][0] + b0)*presc, (C[j][1] + b1)*presc, uh, ul);
            yh0[j*4 + (l & 3)] = uh;
            yl0[j*4 + (l & 3)] = ul;
            split2_pack_f16((C[j][2] + b0)*presc, (C[j][3] + b1)*presc, uh, ul);
            yh1[j*4 + (l & 3)] = uh;
            yl1[j*4 + (l & 3)] = ul;
        }
    } else {
        uint32_t* y0 = (uint32_t*)(g_vh + (size_t)row_lo*DK);
        uint32_t* y1 = (uint32_t*)(g_vh + (size_t)row_hi*DK);
        #pragma unroll
        for (int j = 0; j < 8; j++) {
            int c = j*8 + 2*(l & 3);
            float b0 = bias[c], b1 = bias[c+1];
            uint32_t u;
            CVT_F16X2(u, C[j][1] + b1, C[j][0] + b0);
            y0[j*4 + (l & 3)] = u;
            CVT_F16X2(u, C[j][3] + b1, C[j][2] + b0);
            y1[j*4 + (l & 3)] = u;
        }
    }
}

// ---------------------------------------------------------------------------
// Flash attention split-K (fp16 QK 3-term, PV 1-term; log2 units).
// CTA = 64 q x 128 thr, 3 CTA/SM. dyn smem 55296:
// Qh 0, Ql T, Kh 2T, Kl 3T, V0 4T, V1 5T. (verbatim R13 — mask NOT hoisted)
// ---------------------------------------------------------------------------
__global__ __launch_bounds__(128, 3) void attn_mma_kernel()
{
    extern __shared__ char sbuf[];
    const uint32_t sbase = smem_u32(sbuf);
    const uint32_t oQh = 0, oQl = TILE_B;
    const uint32_t oKh = 2*TILE_B, oKl = 3*TILE_B;

    const int tid = threadIdx.x;
    const int w   = tid >> 5;
    const int l   = tid & 31;
    const int b   = blockIdx.y;
    const int q0  = blockIdx.x * 64;
    const int sp  = blockIdx.z;
    const int t0  = sp * TPS;

    const uint4* gkh = (const uint4*)(g_kh_hi + (size_t)b*SEQ*DK);
    const uint4* gkl = (const uint4*)(g_kh_lo + (size_t)b*SEQ*DK);
    const uint4* gv  = (const uint4*)(g_vh   + (size_t)b*SEQ*DK);

    {
        const uint4* gqh = (const uint4*)(g_qh_hi + (size_t)(b*SEQ + q0)*DK);
        const uint4* gql = (const uint4*)(g_qh_lo + (size_t)(b*SEQ + q0)*DK);
        int k0 = t0*64;
        #pragma unroll
        for (int it = 0; it < 4; it++) {
            int i = tid + it*128;
            int r = i >> 3, c = i & 7;
            uint32_t d = r*RSTRIDE_B + c*16;
            size_t gi = (size_t)(k0 + r)*8 + c;
            CP16(sbase + oQh + d, gqh + i);
            CP16(sbase + oQl + d, gql + i);
            CP16(sbase + oKh + d, gkh + gi);
            CP16(sbase + oKl + d, gkl + gi);
            CP16(sbase + 4*TILE_B + d, gv + gi);
        }
        CP_COMMIT();
        CP_WAIT(0);
    }
    __syncthreads();

    const int arow     = w*16 + (l & 7) + ((l >> 3) & 1)*8;
    const int acolb    = ((l >> 3) & 2)*8;
    const int brow_off = (l & 7) + ((l >> 3) & 2)*4;
    const int bcol_off = ((l >> 3) & 1)*16;
    const int vrow_off = (l & 7) + ((l >> 3) & 1)*8;
    const int vcol_off = ((l >> 4) & 1)*16;

    float O[8][4];
    #pragma unroll
    for (int j = 0; j < 8; j++)
        #pragma unroll
        for (int i = 0; i < 4; i++) O[j][i] = 0.f;
    float mr[2] = {-1e30f, -1e30f};
    float lr[2] = {0.f, 0.f};

    const int q_lo = q0 + w*16 + (l >> 2);
    const int q_hi = q_lo + 8;

    for (int ti = t0; ti < t0 + TPS; ti++) {
        const int k0 = ti*64;
        const bool more = (ti + 1 < t0 + TPS);
        const uint32_t oV = sbase + (4u + (uint32_t)(ti & 1))*TILE_B;

        // ---- S = Q K^T (fp16 3-term) ----
        float S[8][4];
        #pragma unroll
        for (int j = 0; j < 8; j++)
            #pragma unroll
            for (int i = 0; i < 4; i++) S[j][i] = 0.f;

        #pragma unroll
        for (int t = 0; t < 4; t++) {
            uint32_t qh0,qh1,qh2,qh3, ql0,ql1,ql2,ql3;
            uint32_t qa = sbase + oQh + arow*RSTRIDE_B + t*32 + acolb;
            LDSM_X4(qh0,qh1,qh2,qh3, qa);
            LDSM_X4(ql0,ql1,ql2,ql3, qa + TILE_B);
            #pragma unroll
            for (int g = 0; g < 4; g++) {
                uint32_t a = sbase + oKh + (g*16 + brow_off)*RSTRIDE_B + t*32 + bcol_off;
                uint32_t h0,h1,h2,h3, l0,l1,l2,l3;
                LDSM_X4(h0,h1,h2,h3, a);
                LDSM_X4(l0,l1,l2,l3, a + TILE_B);
                MMA16816H(S[2*g],   qh0,qh1,qh2,qh3, h0,h1);
                MMA16816H(S[2*g],   qh0,qh1,qh2,qh3, l0,l1);
                MMA16816H(S[2*g],   ql0,ql1,ql2,ql3, h0,h1);
                MMA16816H(S[2*g+1], qh0,qh1,qh2,qh3, h2,h3);
                MMA16816H(S[2*g+1], qh0,qh1,qh2,qh3, l2,l3);
                MMA16816H(S[2*g+1], ql0,ql1,ql2,ql3, h2,h3);
            }
        }
        __syncthreads();   // K reads complete CTA-wide; PV(ti-1) done by all warps

        // prefetch K(ti+1) and V(ti+1) — land behind softmax + PV
        if (more) {
            uint32_t nV = sbase + (4u + (uint32_t)((ti+1) & 1))*TILE_B;
            #pragma unroll
            for (int it = 0; it < 4; it++) {
                int i = tid + it*128;
                int r = i >> 3, c = i & 7;
                uint32_t d = r*RSTRIDE_B + c*16;
                size_t gi = (size_t)(k0 + 64 + r)*8 + c;
                CP16(sbase + oKh + d, gkh + gi);
                CP16(sbase + oKl + d, gkl + gi);
                CP16(nV + d,          gv  + gi);
            }
            CP_COMMIT();
        }

        // ---- mask ----
        {
            uint2 m0 = *(const uint2*)(g_mpack + (size_t)q_lo*(SEQ/32) + (k0 >> 5));
            uint2 m1 = *(const uint2*)(g_mpack + (size_t)q_hi*(SEQ/32) + (k0 >> 5));
            uint64_t w0 = ((uint64_t)m0.y << 32) | m0.x;
            uint64_t w1 = ((uint64_t)m1.y << 32) | m1.x;
            #pragma unroll
            for (int j = 0; j < 8; j++) {
                int c = j*8 + 2*(l & 3);
                if (!((w0 >> c) & 1))     S[j][0] = -1e9f;
                if (!((w0 >> (c+1)) & 1)) S[j][1] = -1e9f;
                if (!((w1 >> c) & 1))     S[j][2] = -1e9f;
                if (!((w1 >> (c+1)) & 1)) S[j][3] = -1e9f;
            }
        }

        // ---- online softmax (base-2) ----
        float mx0 = -1e30f, mx1 = -1e30f;
        #pragma unroll
        for (int j = 0; j < 8; j++) {
            mx0 = fmaxf(mx0, fmaxf(S[j][0], S[j][1]));
            mx1 = fmaxf(mx1, fmaxf(S[j][2], S[j][3]));
        }
        mx0 = fmaxf(mx0, __shfl_xor_sync(0xffffffffu, mx0, 1));
        mx0 = fmaxf(mx0, __shfl_xor_sync(0xffffffffu, mx0, 2));
        mx1 = fmaxf(mx1, __shfl_xor_sync(0xffffffffu, mx1, 1));
        mx1 = fmaxf(mx1, __shfl_xor_sync(0xffffffffu, mx1, 2));
        float mn0 = fmaxf(mr[0], mx0), mn1 = fmaxf(mr[1], mx1);
        float cr0 = exp2f(mr[0] - mn0), cr1 = exp2f(mr[1] - mn1);
        mr[0] = mn0; mr[1] = mn1;

        float ps0 = 0.f, ps1 = 0.f;
        uint32_t pa[4][4];
        #pragma unroll
        for (int t = 0; t < 4; t++) {
            float p[8];
            #pragma unroll
            for (int u = 0; u < 2; u++) {
                int j = 2*t + u;
                p[4*u+0] = exp2f(S[j][0] - mn0);
                p[4*u+1] = exp2f(S[j][1] - mn0);
                p[4*u+2] = exp2f(S[j][2] - mn1);
                p[4*u+3] = exp2f(S[j][3] - mn1);
                ps0 += p[4*u+0] + p[4*u+1];
                ps1 += p[4*u+2] + p[4*u+3];
            }
            CVT_F16X2(pa[t][0], p[1], p[0]);
            CVT_F16X2(pa[t][1], p[3], p[2]);
            CVT_F16X2(pa[t][2], p[5], p[4]);
            CVT_F16X2(pa[t][3], p[7], p[6]);
        }
        ps0 += __shfl_xor_sync(0xffffffffu, ps0, 1);
        ps0 += __shfl_xor_sync(0xffffffffu, ps0, 2);
        ps1 += __shfl_xor_sync(0xffffffffu, ps1, 1);
        ps1 += __shfl_xor_sync(0xffffffffu, ps1, 2);
        lr[0] = lr[0]*cr0 + ps0;
        lr[1] = lr[1]*cr1 + ps1;

        #pragma unroll
        for (int j = 0; j < 8; j++) {
            O[j][0] *= cr0; O[j][1] *= cr0;
            O[j][2] *= cr1; O[j][3] *= cr1;
        }

        // ---- O += P V (fp16 1-term; V(ti) arrived before this iteration) ----
        #pragma unroll
        for (int t = 0; t < 4; t++) {
            #pragma unroll
            for (int g = 0; g < 4; g++) {
                uint32_t a = oV + (t*16 + vrow_off)*RSTRIDE_B + g*32 + vcol_off;
                uint32_t h0,h1,h2,h3;
                LDSM_X4_T(h0,h1,h2,h3, a);
                MMA16816H(O[2*g],   pa[t][0],pa[t][1],pa[t][2],pa[t][3], h0,h1);
                MMA16816H(O[2*g+1], pa[t][0],pa[t][1],pa[t][2],pa[t][3], h2,h3);
            }
        }

        if (more) {
            CP_WAIT(0);        // K(ti+1) and V(ti+1) arrived
            __syncthreads();   // visible to all; all reads of K/V done
        }
    }

    // ---- write unnormalized partials + (m, l) ----
    {
        float* po0 = g_part + ((size_t)sp*MTOT + b*SEQ + q_lo)*DK;
        float* po1 = g_part + ((size_t)sp*MTOT + b*SEQ + q_hi)*DK;
        #pragma unroll
        for (int j = 0; j < 8; j++) {
            int c = j*8 + 2*(l & 3);
            float2 v0 = { O[j][0], O[j][1] };
            float2 v1 = { O[j][2], O[j][3] };
            *(float2*)(po0 + c) = v0;
            *(float2*)(po1 + c) = v1;
        }
        if ((l & 3) == 0) {
            g_ml[(size_t)sp*MTOT + b*SEQ + q_lo] = make_float2(mr[0], lr[0]);
            g_ml[(size_t)sp*MTOT + b*SEQ + q_hi] = make_float2(mr[1], lr[1]);
        }
    }
}

// ---------------------------------------------------------------------------
// split-K merge -> bf16 hi/lo (verbatim R13)
// ---------------------------------------------------------------------------
__global__ __launch_bounds__(256) void merge_kernel()
{
    int idx = blockIdx.x * 256 + threadIdx.x;
    int row = idx >> 4;
    int c4  = (idx & 15) * 4;

    float2 ml0 = g_ml[row];
    float2 ml1 = g_ml[MTOT + row];
    float M = fmaxf(ml0.x, ml1.x);
    float a0 = exp2f(ml0.x - M);
    float a1 = exp2f(ml1.x - M);
    float inv = 1.f / (ml0.y*a0 + ml1.y*a1);

    float4 o0 = *(const float4*)(g_part + (size_t)row*DK + c4);
    float4 o1 = *(const float4*)(g_part + ((size_t)MTOT + row)*DK + c4);
    uint2 uh, ul;
    split2_pack((o0.x*a0 + o1.x*a1)*inv, (o0.y*a0 + o1.y*a1)*inv, uh.x, ul.x);
    split2_pack((o0.z*a0 + o1.z*a1)*inv, (o0.w*a0 + o1.w*a1)*inv, uh.y, ul.y);
    ((uint2*)g_aoh)[idx] = uh;
    ((uint2*)g_aol)[idx] = ul;
}

// ---------------------------------------------------------------------------
// Output projection: out[M,1024] = AO[M,64] @ Wo[1024,64]^T + bo
// grid (MTOT/64, 2): y selects N-half (8 chunks of 64). Only change vs R13.
// dyn smem 55296: Ah 0, Al T, Wbuf0 {2T,3T}, Wbuf1 {4T,5T}.
// ---------------------------------------------------------------------------
__global__ __launch_bounds__(128, 3) void oproj_mma_kernel(
    const float* __restrict__ bo, float* __restrict__ out)
{
    extern __shared__ char psm[];
    const uint32_t sb = smem_u32(psm);

    const int tid = threadIdx.x;
    const int w = tid >> 5, l = tid & 31;
    const int row0 = blockIdx.x * 64;
    const int nh   = blockIdx.y;          // 0 or 1: N chunks nh*8 .. nh*8+7

    const __nv_bfloat16* gwh = g_wh + (size_t)3*65536;
    const __nv_bfloat16* gwl = g_wl + (size_t)3*65536;

    {
        int nb0 = nh*512;
        #pragma unroll
        for (int it = 0; it < 4; it++) {
            int i = tid + it*128;
            int r = i >> 3, c = i & 7;
            uint32_t d = r*RSTRIDE_B + c*16;
            CP16(sb + d,          ((const uint4*)(g_aoh + (size_t)(row0 + r)*DK)) + c);
            CP16(sb + TILE_B + d, ((const uint4*)(g_aol + (size_t)(row0 + r)*DK)) + c);
            CP16(sb + 2*TILE_B + d, ((const uint4*)(gwh + (size_t)(nb0 + r)*DK)) + c);
            CP16(sb + 3*TILE_B + d, ((const uint4*)(gwl + (size_t)(nb0 + r)*DK)) + c);
        }
        CP_COMMIT();
        CP_WAIT(0);
    }
    __syncthreads();

    uint32_t oa_h[4][4], oa_l[4][4];
    {
        int row = w*16 + (l & 7) + ((l >> 3) & 1)*8;
        int colb_off = ((l >> 3) & 2)*8;
        #pragma unroll
        for (int t = 0; t < 4; t++) {
            uint32_t a = sb + row*RSTRIDE_B + t*32 + colb_off;
            LDSM_X4(oa_h[t][0], oa_h[t][1], oa_h[t][2], oa_h[t][3], a);
            LDSM_X4(oa_l[t][0], oa_l[t][1], oa_l[t][2], oa_l[t][3], a + TILE_B);
        }
    }

    const int brow  = (l & 7) + ((l >> 3) & 2)*4;
    const int bcolb = ((l >> 3) & 1)*16;
    const int row_lo = row0 + w*16 + (l >> 2);
    const int row_hi = row_lo + 8;

    for (int nc = 0; nc < 8; nc++) {
        const int n0 = nh*512 + nc*64;
        if (nc + 1 < 8) {
            uint32_t wb = sb + 2*TILE_B + ((nc+1)&1)*2*TILE_B;
            #pragma unroll
            for (int it = 0; it < 4; it++) {
                int i = tid + it*128;
                int r = i >> 3, c = i & 7;
                uint32_t d = r*RSTRIDE_B + c*16;
                CP16(wb + d,          ((const uint4*)(gwh + (size_t)(n0 + 64 + r)*DK)) + c);
                CP16(wb + TILE_B + d, ((const uint4*)(gwl + (size_t)(n0 + 64 + r)*DK)) + c);
            }
            CP_COMMIT();
            CP_WAIT(1);
        } else {
            CP_WAIT(0);
        }
        __syncthreads();

        const uint32_t aWh = sb + 2*TILE_B + (nc&1)*2*TILE_B;
        float C[8][4];
        #pragma unroll
        for (int j = 0; j < 8; j++)
            #pragma unroll
            for (int i = 0; i < 4; i++) C[j][i] = 0.f;

        #pragma unroll
        for (int t = 0; t < 4; t++) {
            #pragma unroll
            for (int g = 0; g < 4; g++) {
                uint32_t ba = aWh + (g*16 + brow)*RSTRIDE_B + t*32 + bcolb;
                uint32_t h0,h1,h2,h3, w0,w1,w2,w3;
                LDSM_X4(h0,h1,h2,h3, ba);
                LDSM_X4(w0,w1,w2,w3, ba + TILE_B);
                MMA16816(C[2*g],   oa_h[t][0],oa_h[t][1],oa_h[t][2],oa_h[t][3], h0,h1);
                MMA16816(C[2*g],   oa_h[t][0],oa_h[t][1],oa_h[t][2],oa_h[t][3], w0,w1);
                MMA16816(C[2*g],   oa_l[t][0],oa_l[t][1],oa_l[t][2],oa_l[t][3], h0,h1);
                MMA16816(C[2*g+1], oa_h[t][0],oa_h[t][1],oa_h[t][2],oa_h[t][3], h2,h3);
                MMA16816(C[2*g+1], oa_h[t][0],oa_h[t][1],oa_h[t][2],oa_h[t][3], w2,w3);
                MMA16816(C[2*g+1], oa_l[t][0],oa_l[t][1],oa_l[t][2],oa_l[t][3], h2,h3);
            }
        }

        float2* po0 = (float2*)(out + (size_t)row_lo*DM + n0);
        float2* po1 = (float2*)(out + (size_t)row_hi*DM + n0);
        #pragma unroll
        for (int j = 0; j < 8; j++) {
            int c = j*8 + 2*(l & 3);
            float b0v = bo[n0 + c], b1v = bo[n0 + c + 1];
            float2 v0 = { C[j][0] + b0v, C[j][1] + b1v };
            float2 v1 = { C[j][2] + b0v, C[j][3] + b1v };
            po0[j*4 + (l & 3)] = v0;
            po1[j*4 + (l & 3)] = v1;
        }
        __syncthreads();
    }
}

// ---------------------------------------------------------------------------
extern "C" void kernel_launch(void* const* d_in, const int* in_sizes, int n_in,
                              void* d_out, int out_size)
{
    const float* q    = (const float*)d_in[0];
    const float* k    = (const float*)d_in[1];
    const float* v    = (const float*)d_in[2];
    const int*   mask = (const int*)  d_in[3];
    const float* Wq   = (const float*)d_in[4];
    const float* bq   = (const float*)d_in[5];
    const float* Wk   = (const float*)d_in[6];
    const float* bk   = (const float*)d_in[7];
    const float* Wv   = (const float*)d_in[8];
    const float* bv   = (const float*)d_in[9];
    const float* Wo   = (const float*)d_in[10];
    const float* bo   = (const float*)d_in[11];
    float* out = (float*)d_out;

    const int smem6 = 6*TILE_B;    // 55296
    cudaFuncSetAttribute(proj_mma_kernel,
                         cudaFuncAttributeMaxDynamicSharedMemorySize, smem6);
    cudaFuncSetAttribute(attn_mma_kernel,
                         cudaFuncAttributeMaxDynamicSharedMemorySize, smem6);
    cudaFuncSetAttribute(oproj_mma_kernel,
                         cudaFuncAttributeMaxDynamicSharedMemorySize, smem6);

    pack_mask_kernel<<<SEQ*SEQ/4/256, 256>>>(mask);
    split_w_kernel<<<dim3(64, 4), 256>>>(Wq, Wk, Wv, Wo);

    proj_mma_kernel<<<dim3(MTOT/64, 3), 128, smem6>>>(q, k, v, bq, bk, bv);

    attn_mma_kernel<<<dim3(SEQ/64, BB, NSPLIT), 128, smem6>>>();

    merge_kernel<<<MTOT/16, 256>>>();

    oproj_mma_kernel<<<dim3(MTOT/64, 2), 128, smem6>>>(bo, out);
}

// round 17
// speedup vs baseline: 1.0882x; 1.0504x over previous
#include <cuda_runtime.h>
#include <cuda_bf16.h>
#include <cuda_fp16.h>
#include <stdint.h>

#define BB 4
#define SEQ 4096
#define DM 1024
#define DK 64
#define MTOT (BB*SEQ)
#define NSPLIT 2
#define TPS (SEQ/64/NSPLIT)

#define RSTRIDE_B 144
#define TILE_B    9216

// ---------------------------------------------------------------------------
// Scratch (device globals — allocation-free)
// ---------------------------------------------------------------------------
__device__ alignas(16) uint16_t g_qh[MTOT*DK];           // fp16 single (Q)
__device__ alignas(16) uint16_t g_kh_hi[MTOT*DK];
__device__ alignas(16) uint16_t g_kh_lo[MTOT*DK];
__device__ alignas(16) uint16_t g_vh[MTOT*DK];           // fp16 single
__device__ alignas(16) __nv_bfloat16 g_aoh[MTOT*DK];
__device__ alignas(16) __nv_bfloat16 g_aol[MTOT*DK];
__device__ alignas(16) __nv_bfloat16 g_wh[4*64*1024];
__device__ alignas(16) __nv_bfloat16 g_wl[4*64*1024];
__device__ alignas(16) float g_part[NSPLIT*MTOT*DK];
__device__ alignas(8)  float2 g_ml[NSPLIT*MTOT];
__device__ uint32_t g_mpack[SEQ*SEQ/32];

// ---------------------------------------------------------------------------
// helpers
// ---------------------------------------------------------------------------
__device__ __forceinline__ uint32_t smem_u32(const void* p) {
    uint32_t a;
    asm("{ .reg .u64 t; cvta.to.shared.u64 t, %1; cvt.u32.u64 %0, t; }"
        : "=r"(a) : "l"(p));
    return a;
}
__device__ __forceinline__ void split2_pack(float v0, float v1,
                                            uint32_t& ph, uint32_t& pl) {
    uint32_t u0 = __float_as_uint(v0), u1 = __float_as_uint(v1);
    float h0 = __uint_as_float(u0 & 0xFFFF0000u);
    float h1 = __uint_as_float(u1 & 0xFFFF0000u);
    ph = __byte_perm(u0, u1, 0x7632);
    pl = __byte_perm(__float_as_uint(v0 - h0), __float_as_uint(v1 - h1), 0x7632);
}
#define CVT_F16X2(d, vhi, vlo) \
    asm("cvt.rn.f16x2.f32 %0, %1, %2;" : "=r"(d) : "f"(vhi), "f"(vlo))
__device__ __forceinline__ void split2_pack_f16(float v0, float v1,
                                                uint32_t& ph, uint32_t& pl) {
    __half h0 = __float2half_rn(v0), h1 = __float2half_rn(v1);
    __half2 H = __halves2half2(h0, h1);
    ph = *reinterpret_cast<uint32_t*>(&H);
    CVT_F16X2(pl, v1 - __half2float(h1), v0 - __half2float(h0));
}

#define LDSM_X4(r0,r1,r2,r3,addr) \
    asm volatile("ldmatrix.sync.aligned.m8n8.x4.shared.b16 {%0,%1,%2,%3}, [%4];" \
        : "=r"(r0), "=r"(r1), "=r"(r2), "=r"(r3) : "r"(addr))

#define LDSM_X4_T(r0,r1,r2,r3,addr) \
    asm volatile("ldmatrix.sync.aligned.m8n8.x4.trans.shared.b16 {%0,%1,%2,%3}, [%4];" \
        : "=r"(r0), "=r"(r1), "=r"(r2), "=r"(r3) : "r"(addr))

#define MMA16816(c, a0,a1,a2,a3, b0,b1) \
    asm volatile("mma.sync.aligned.m16n8k16.row.col.f32.bf16.bf16.f32 " \
        "{%0,%1,%2,%3},{%4,%5,%6,%7},{%8,%9},{%0,%1,%2,%3};" \
        : "+f"((c)[0]), "+f"((c)[1]), "+f"((c)[2]), "+f"((c)[3]) \
        : "r"(a0), "r"(a1), "r"(a2), "r"(a3), "r"(b0), "r"(b1))

#define MMA16816H(c, a0,a1,a2,a3, b0,b1) \
    asm volatile("mma.sync.aligned.m16n8k16.row.col.f32.f16.f16.f32 " \
        "{%0,%1,%2,%3},{%4,%5,%6,%7},{%8,%9},{%0,%1,%2,%3};" \
        : "+f"((c)[0]), "+f"((c)[1]), "+f"((c)[2]), "+f"((c)[3]) \
        : "r"(a0), "r"(a1), "r"(a2), "r"(a3), "r"(b0), "r"(b1))

#define CP16(dst_u32, src_ptr) \
    asm volatile("cp.async.cg.shared.global [%0], [%1], 16;" \
        :: "r"(dst_u32), "l"(src_ptr) : "memory")
#define CP_COMMIT() asm volatile("cp.async.commit_group;" ::: "memory")
#define CP_WAIT(N)  asm volatile("cp.async.wait_group %0;" :: "n"(N) : "memory")

// ---------------------------------------------------------------------------
// mask bit-pack (int4 vectorized)
// ---------------------------------------------------------------------------
__global__ __launch_bounds__(256) void pack_mask_kernel(const int* __restrict__ m)
{
    int t = blockIdx.x * 256 + threadIdx.x;
    int lane = threadIdx.x & 31;
    int4 mv = ((const int4*)m)[t];
    uint32_t nib = (mv.x != 0 ? 1u : 0u) | (mv.y != 0 ? 2u : 0u)
                 | (mv.z != 0 ? 4u : 0u) | (mv.w != 0 ? 8u : 0u);
    uint32_t v = nib << (4*(lane & 7));
    v |= __shfl_xor_sync(0xffffffffu, v, 1);
    v |= __shfl_xor_sync(0xffffffffu, v, 2);
    v |= __shfl_xor_sync(0xffffffffu, v, 4);
    if ((lane & 7) == 0) g_mpack[t >> 3] = v;
}

// ---------------------------------------------------------------------------
// weight split (bf16 trunc). z: 0=Wq 1=Wk 2=Wv 3=Wo
// ---------------------------------------------------------------------------
__global__ __launch_bounds__(256) void split_w_kernel(
    const float* __restrict__ Wq, const float* __restrict__ Wk,
    const float* __restrict__ Wv, const float* __restrict__ Wo)
{
    int z = blockIdx.y;
    const float* W = (z == 0) ? Wq : (z == 1) ? Wk : (z == 2) ? Wv : Wo;
    int i4 = blockIdx.x * 256 + threadIdx.x;
    float4 wv = ((const float4*)W)[i4];
    uint2 uh, ul;
    split2_pack(wv.x, wv.y, uh.x, ul.x);
    split2_pack(wv.z, wv.w, uh.y, ul.y);
    ((uint2*)(g_wh + (size_t)z*65536))[i4] = uh;
    ((uint2*)(g_wl + (size_t)z*65536))[i4] = ul;
}

// ---------------------------------------------------------------------------
// Q/K/V projection (bf16x3 internally). Epilogue: K -> fp16 hi/lo (rn),
// Q/V -> fp16 single (rn). CTA: 64 rows, 128 threads; grid (MTOT/64, 3).
// ---------------------------------------------------------------------------
__global__ __launch_bounds__(128, 3) void proj_mma_kernel(
    const float* __restrict__ q, const float* __restrict__ k, const float* __restrict__ v,
    const float* __restrict__ bq, const float* __restrict__ bk, const float* __restrict__ bv)
{
    extern __shared__ char psm[];
    const uint32_t sb = smem_u32(psm);
    const uint32_t oXh = 0, oXl = TILE_B;

    const int tid = threadIdx.x;
    const int w = tid >> 5, l = tid & 31;
    const int z = blockIdx.y;
    const int row0 = blockIdx.x * 64;

    const float* x    = (z == 0) ? q  : (z == 1) ? k  : v;
    const float* bias = (z == 0) ? bq : (z == 1) ? bk : bv;
    const __nv_bfloat16* gwh = g_wh + (size_t)z*65536;
    const __nv_bfloat16* gwl = g_wl + (size_t)z*65536;
    const float presc = (z == 0) ? 0.125f*1.44269504f : 1.0f;

    const int arow  = w*16 + (l & 7) + ((l >> 3) & 1)*8;
    const int acolb = ((l >> 3) & 2)*8;
    const int brow  = (l & 7) + ((l >> 3) & 2)*4;
    const int bcolb = ((l >> 3) & 1)*16;

    const int xr_r = tid >> 4;
    const int xr_c = tid & 15;

    float C[8][4];
    #pragma unroll
    for (int j = 0; j < 8; j++)
        #pragma unroll
        for (int i = 0; i < 4; i++) C[j][i] = 0.f;

    {
        #pragma unroll
        for (int it = 0; it < 4; it++) {
            int i = tid + it*128;
            int r = i >> 3, c = i & 7;
            uint32_t d = r*RSTRIDE_B + c*16;
            CP16(sb + 2*TILE_B + d, ((const uint4*)(gwh + (size_t)r*DM)) + c);
            CP16(sb + 3*TILE_B + d, ((const uint4*)(gwl + (size_t)r*DM)) + c);
        }
        CP_COMMIT();
    }
    float4 xr[8];
    #pragma unroll
    for (int it = 0; it < 8; it++) {
        int r = xr_r + it*8;
        xr[it] = *(const float4*)(x + (size_t)(row0 + r)*DM + xr_c*4);
    }

    for (int k0 = 0; k0 < DM; k0 += 64) {
        int kc = k0 >> 6;
        #pragma unroll
        for (int it = 0; it < 8; it++) {
            int r = xr_r + it*8;
            uint2 uh, ul;
            split2_pack(xr[it].x, xr[it].y, uh.x, ul.x);
            split2_pack(xr[it].z, xr[it].w, uh.y, ul.y);
            *(uint2*)(psm + oXh + r*RSTRIDE_B + xr_c*8) = uh;
            *(uint2*)(psm + oXl + r*RSTRIDE_B + xr_c*8) = ul;
        }
        if (k0 + 64 < DM) {
            #pragma unroll
            for (int it = 0; it < 8; it++) {
                int r = xr_r + it*8;
                xr[it] = *(const float4*)(x + (size_t)(row0 + r)*DM + k0 + 64 + xr_c*4);
            }
            uint32_t wb = sb + 2*TILE_B + ((kc+1)&1)*2*TILE_B;
            #pragma unroll
            for (int it = 0; it < 4; it++) {
                int i = tid + it*128;
                int r = i >> 3, c = i & 7;
                uint32_t d = r*RSTRIDE_B + c*16;
                CP16(wb + d,          ((const uint4*)(gwh + (size_t)r*DM + k0 + 64)) + c);
                CP16(wb + TILE_B + d, ((const uint4*)(gwl + (size_t)r*DM + k0 + 64)) + c);
            }
            CP_COMMIT();
            CP_WAIT(1);
        } else {
            CP_WAIT(0);
        }
        __syncthreads();

        const uint32_t aWh = sb + 2*TILE_B + (kc&1)*2*TILE_B;
        #pragma unroll
        for (int t = 0; t < 4; t++) {
            uint32_t ah[4], al[4];
            uint32_t aa = sb + oXh + arow*RSTRIDE_B + t*32 + acolb;
            LDSM_X4(ah[0], ah[1], ah[2], ah[3], aa);
            LDSM_X4(al[0], al[1], al[2], al[3], aa + TILE_B);
            #pragma unroll
            for (int g = 0; g < 4; g++) {
                uint32_t ba = aWh + (g*16 + brow)*RSTRIDE_B + t*32 + bcolb;
                uint32_t h0,h1,h2,h3, w0,w1,w2,w3;
                LDSM_X4(h0,h1,h2,h3, ba);
                LDSM_X4(w0,w1,w2,w3, ba + TILE_B);
                MMA16816(C[2*g],   ah[0],ah[1],ah[2],ah[3], h0,h1);
                MMA16816(C[2*g],   ah[0],ah[1],ah[2],ah[3], w0,w1);
                MMA16816(C[2*g],   al[0],al[1],al[2],al[3], h0,h1);
                MMA16816(C[2*g+1], ah[0],ah[1],ah[2],ah[3], h2,h3);
                MMA16816(C[2*g+1], ah[0],ah[1],ah[2],ah[3], w2,w3);
                MMA16816(C[2*g+1], al[0],al[1],al[2],al[3], h2,h3);
            }
        }
        __syncthreads();
    }

    const int row_lo = row0 + w*16 + (l >> 2);
    const int row_hi = row_lo + 8;
    if (z == 1) {
        uint32_t* yh0 = (uint32_t*)(g_kh_hi + (size_t)row_lo*DK);
        uint32_t* yl0 = (uint32_t*)(g_kh_lo + (size_t)row_lo*DK);
        uint32_t* yh1 = (uint32_t*)(g_kh_hi + (size_t)row_hi*DK);
        uint32_t* yl1 = (uint32_t*)(g_kh_lo + (size_t)row_hi*DK);
        #pragma unroll
        for (int j = 0; j < 8; j++) {
            int c = j*8 + 2*(l & 3);
            float b0 = bias[c], b1 = bias[c+1];
            uint32_t uh, ul;
            split2_pack_f16(C[j][0] + b0, C[j][1] + b1, uh, ul);
            yh0[j*4 + (l & 3)] = uh;
            yl0[j*4 + (l & 3)] = ul;
            split2_pack_f16(C[j][2] + b0, C[j][3] + b1, uh, ul);
            yh1[j*4 + (l & 3)] = uh;
            yl1[j*4 + (l & 3)] = ul;
        }
    } else {
        uint16_t* y = (z == 0) ? g_qh : g_vh;
        uint32_t* y0 = (uint32_t*)(y + (size_t)row_lo*DK);
        uint32_t* y1 = (uint32_t*)(y + (size_t)row_hi*DK);
        #pragma unroll
        for (int j = 0; j < 8; j++) {
            int c = j*8 + 2*(l & 3);
            float b0 = bias[c], b1 = bias[c+1];
            uint32_t u;
            CVT_F16X2(u, (C[j][1] + b1)*presc, (C[j][0] + b0)*presc);
            y0[j*4 + (l & 3)] = u;
            CVT_F16X2(u, (C[j][3] + b1)*presc, (C[j][2] + b0)*presc);
            y1[j*4 + (l & 3)] = u;
        }
    }
}

// ---------------------------------------------------------------------------
// Flash attention split-K (fp16: Q single, QK 2-term, PV 1-term; log2 units).
// CTA = 64 q x 128 thr, 3 CTA/SM. dyn smem 46080:
// Q 0, Kh T, Kl 2T, V0 3T, V1 4T. Schedule identical to R13.
// ---------------------------------------------------------------------------
__global__ __launch_bounds__(128, 3) void attn_mma_kernel()
{
    extern __shared__ char sbuf[];
    const uint32_t sbase = smem_u32(sbuf);
    const uint32_t oQ  = 0;
    const uint32_t oKh = TILE_B, oKl = 2*TILE_B;

    const int tid = threadIdx.x;
    const int w   = tid >> 5;
    const int l   = tid & 31;
    const int b   = blockIdx.y;
    const int q0  = blockIdx.x * 64;
    const int sp  = blockIdx.z;
    const int t0  = sp * TPS;

    const uint4* gkh = (const uint4*)(g_kh_hi + (size_t)b*SEQ*DK);
    const uint4* gkl = (const uint4*)(g_kh_lo + (size_t)b*SEQ*DK);
    const uint4* gv  = (const uint4*)(g_vh   + (size_t)b*SEQ*DK);

    {
        const uint4* gq = (const uint4*)(g_qh + (size_t)(b*SEQ + q0)*DK);
        int k0 = t0*64;
        #pragma unroll
        for (int it = 0; it < 4; it++) {
            int i = tid + it*128;
            int r = i >> 3, c = i & 7;
            uint32_t d = r*RSTRIDE_B + c*16;
            size_t gi = (size_t)(k0 + r)*8 + c;
            CP16(sbase + oQ  + d, gq  + i);
            CP16(sbase + oKh + d, gkh + gi);
            CP16(sbase + oKl + d, gkl + gi);
            CP16(sbase + 3*TILE_B + d, gv + gi);
        }
        CP_COMMIT();
        CP_WAIT(0);
    }
    __syncthreads();

    const int arow     = w*16 + (l & 7) + ((l >> 3) & 1)*8;
    const int acolb    = ((l >> 3) & 2)*8;
    const int brow_off = (l & 7) + ((l >> 3) & 2)*4;
    const int bcol_off = ((l >> 3) & 1)*16;
    const int vrow_off = (l & 7) + ((l >> 3) & 1)*8;
    const int vcol_off = ((l >> 4) & 1)*16;

    float O[8][4];
    #pragma unroll
    for (int j = 0; j < 8; j++)
        #pragma unroll
        for (int i = 0; i < 4; i++) O[j][i] = 0.f;
    float mr[2] = {-1e30f, -1e30f};
    float lr[2] = {0.f, 0.f};

    const int q_lo = q0 + w*16 + (l >> 2);
    const int q_hi = q_lo + 8;

    for (int ti = t0; ti < t0 + TPS; ti++) {
        const int k0 = ti*64;
        const bool more = (ti + 1 < t0 + TPS);
        const uint32_t oV = sbase + (3u + (uint32_t)(ti & 1))*TILE_B;

        // ---- S = Q K^T (fp16 2-term: qh·kh + qh·kl) ----
        float S[8][4];
        #pragma unroll
        for (int j = 0; j < 8; j++)
            #pragma unroll
            for (int i = 0; i < 4; i++) S[j][i] = 0.f;

        #pragma unroll
        for (int t = 0; t < 4; t++) {
            uint32_t qh0,qh1,qh2,qh3;
            uint32_t qa = sbase + oQ + arow*RSTRIDE_B + t*32 + acolb;
            LDSM_X4(qh0,qh1,qh2,qh3, qa);
            #pragma unroll
            for (int g = 0; g < 4; g++) {
                uint32_t a = sbase + oKh + (g*16 + brow_off)*RSTRIDE_B + t*32 + bcol_off;
                uint32_t h0,h1,h2,h3, l0,l1,l2,l3;
                LDSM_X4(h0,h1,h2,h3, a);
                LDSM_X4(l0,l1,l2,l3, a + TILE_B);
                MMA16816H(S[2*g],   qh0,qh1,qh2,qh3, h0,h1);
                MMA16816H(S[2*g],   qh0,qh1,qh2,qh3, l0,l1);
                MMA16816H(S[2*g+1], qh0,qh1,qh2,qh3, h2,h3);
                MMA16816H(S[2*g+1], qh0,qh1,qh2,qh3, l2,l3);
            }
        }
        __syncthreads();   // K reads complete CTA-wide; PV(ti-1) done by all warps

        // prefetch K(ti+1) and V(ti+1) — land behind softmax + PV
        if (more) {
            uint32_t nV = sbase + (3u + (uint32_t)((ti+1) & 1))*TILE_B;
            #pragma unroll
            for (int it = 0; it < 4; it++) {
                int i = tid + it*128;
                int r = i >> 3, c = i & 7;
                uint32_t d = r*RSTRIDE_B + c*16;
                size_t gi = (size_t)(k0 + 64 + r)*8 + c;
                CP16(sbase + oKh + d, gkh + gi);
                CP16(sbase + oKl + d, gkl + gi);
                CP16(nV + d,          gv  + gi);
            }
            CP_COMMIT();
        }

        // ---- mask ----
        {
            uint2 m0 = *(const uint2*)(g_mpack + (size_t)q_lo*(SEQ/32) + (k0 >> 5));
            uint2 m1 = *(const uint2*)(g_mpack + (size_t)q_hi*(SEQ/32) + (k0 >> 5));
            uint64_t w0 = ((uint64_t)m0.y << 32) | m0.x;
            uint64_t w1 = ((uint64_t)m1.y << 32) | m1.x;
            #pragma unroll
            for (int j = 0; j < 8; j++) {
                int c = j*8 + 2*(l & 3);
                if (!((w0 >> c) & 1))     S[j][0] = -1e9f;
                if (!((w0 >> (c+1)) & 1)) S[j][1] = -1e9f;
                if (!((w1 >> c) & 1))     S[j][2] = -1e9f;
                if (!((w1 >> (c+1)) & 1)) S[j][3] = -1e9f;
            }
        }

        // ---- online softmax (base-2) ----
        float mx0 = -1e30f, mx1 = -1e30f;
        #pragma unroll
        for (int j = 0; j < 8; j++) {
            mx0 = fmaxf(mx0, fmaxf(S[j][0], S[j][1]));
            mx1 = fmaxf(mx1, fmaxf(S[j][2], S[j][3]));
        }
        mx0 = fmaxf(mx0, __shfl_xor_sync(0xffffffffu, mx0, 1));
        mx0 = fmaxf(mx0, __shfl_xor_sync(0xffffffffu, mx0, 2));
        mx1 = fmaxf(mx1, __shfl_xor_sync(0xffffffffu, mx1, 1));
        mx1 = fmaxf(mx1, __shfl_xor_sync(0xffffffffu, mx1, 2));
        float mn0 = fmaxf(mr[0], mx0), mn1 = fmaxf(mr[1], mx1);
        float cr0 = exp2f(mr[0] - mn0), cr1 = exp2f(mr[1] - mn1);
        mr[0] = mn0; mr[1] = mn1;

        float ps0 = 0.f, ps1 = 0.f;
        uint32_t pa[4][4];
        #pragma unroll
        for (int t = 0; t < 4; t++) {
            float p[8];
            #pragma unroll
            for (int u = 0; u < 2; u++) {
                int j = 2*t + u;
                p[4*u+0] = exp2f(S[j][0] - mn0);
                p[4*u+1] = exp2f(S[j][1] - mn0);
                p[4*u+2] = exp2f(S[j][2] - mn1);
                p[4*u+3] = exp2f(S[j][3] - mn1);
                ps0 += p[4*u+0] + p[4*u+1];
                ps1 += p[4*u+2] + p[4*u+3];
            }
            CVT_F16X2(pa[t][0], p[1], p[0]);
            CVT_F16X2(pa[t][1], p[3], p[2]);
            CVT_F16X2(pa[t][2], p[5], p[4]);
            CVT_F16X2(pa[t][3], p[7], p[6]);
        }
        ps0 += __shfl_xor_sync(0xffffffffu, ps0, 1);
        ps0 += __shfl_xor_sync(0xffffffffu, ps0, 2);
        ps1 += __shfl_xor_sync(0xffffffffu, ps1, 1);
        ps1 += __shfl_xor_sync(0xffffffffu, ps1, 2);
        lr[0] = lr[0]*cr0 + ps0;
        lr[1] = lr[1]*cr1 + ps1;

        #pragma unroll
        for (int j = 0; j < 8; j++) {
            O[j][0] *= cr0; O[j][1] *= cr0;
            O[j][2] *= cr1; O[j][3] *= cr1;
        }

        // ---- O += P V (fp16 1-term) ----
        #pragma unroll
        for (int t = 0; t < 4; t++) {
            #pragma unroll
            for (int g = 0; g < 4; g++) {
                uint32_t a = oV + (t*16 + vrow_off)*RSTRIDE_B + g*32 + vcol_off;
                uint32_t h0,h1,h2,h3;
                LDSM_X4_T(h0,h1,h2,h3, a);
                MMA16816H(O[2*g],   pa[t][0],pa[t][1],pa[t][2],pa[t][3], h0,h1);
                MMA16816H(O[2*g+1], pa[t][0],pa[t][1],pa[t][2],pa[t][3], h2,h3);
            }
        }

        if (more) {
            CP_WAIT(0);
            __syncthreads();
        }
    }

    // ---- write unnormalized partials + (m, l) ----
    {
        float* po0 = g_part + ((size_t)sp*MTOT + b*SEQ + q_lo)*DK;
        float* po1 = g_part + ((size_t)sp*MTOT + b*SEQ + q_hi)*DK;
        #pragma unroll
        for (int j = 0; j < 8; j++) {
            int c = j*8 + 2*(l & 3);
            float2 v0 = { O[j][0], O[j][1] };
            float2 v1 = { O[j][2], O[j][3] };
            *(float2*)(po0 + c) = v0;
            *(float2*)(po1 + c) = v1;
        }
        if ((l & 3) == 0) {
            g_ml[(size_t)sp*MTOT + b*SEQ + q_lo] = make_float2(mr[0], lr[0]);
            g_ml[(size_t)sp*MTOT + b*SEQ + q_hi] = make_float2(mr[1], lr[1]);
        }
    }
}

// ---------------------------------------------------------------------------
// split-K merge -> bf16 hi/lo
// ---------------------------------------------------------------------------
__global__ __launch_bounds__(256) void merge_kernel()
{
    int idx = blockIdx.x * 256 + threadIdx.x;
    int row = idx >> 4;
    int c4  = (idx & 15) * 4;

    float2 ml0 = g_ml[row];
    float2 ml1 = g_ml[MTOT + row];
    float M = fmaxf(ml0.x, ml1.x);
    float a0 = exp2f(ml0.x - M);
    float a1 = exp2f(ml1.x - M);
    float inv = 1.f / (ml0.y*a0 + ml1.y*a1);

    float4 o0 = *(const float4*)(g_part + (size_t)row*DK + c4);
    float4 o1 = *(const float4*)(g_part + ((size_t)MTOT + row)*DK + c4);
    uint2 uh, ul;
    split2_pack((o0.x*a0 + o1.x*a1)*inv, (o0.y*a0 + o1.y*a1)*inv, uh.x, ul.x);
    split2_pack((o0.z*a0 + o1.z*a1)*inv, (o0.w*a0 + o1.w*a1)*inv, uh.y, ul.y);
    ((uint2*)g_aoh)[idx] = uh;
    ((uint2*)g_aol)[idx] = ul;
}

// ---------------------------------------------------------------------------
// Output projection: out[M,1024] = AO[M,64] @ Wo[1024,64]^T + bo
// (verbatim R13: grid MTOT/64, 16 N-chunks per CTA)
// ---------------------------------------------------------------------------
__global__ __launch_bounds__(128, 3) void oproj_mma_kernel(
    const float* __restrict__ bo, float* __restrict__ out)
{
    extern __shared__ char psm[];
    const uint32_t sb = smem_u32(psm);

    const int tid = threadIdx.x;
    const int w = tid >> 5, l = tid & 31;
    const int row0 = blockIdx.x * 64;

    const __nv_bfloat16* gwh = g_wh + (size_t)3*65536;
    const __nv_bfloat16* gwl = g_wl + (size_t)3*65536;

    {
        #pragma unroll
        for (int it = 0; it < 4; it++) {
            int i = tid + it*128;
            int r = i >> 3, c = i & 7;
            uint32_t d = r*RSTRIDE_B + c*16;
            CP16(sb + d,          ((const uint4*)(g_aoh + (size_t)(row0 + r)*DK)) + c);
            CP16(sb + TILE_B + d, ((const uint4*)(g_aol + (size_t)(row0 + r)*DK)) + c);
            CP16(sb + 2*TILE_B + d, ((const uint4*)(gwh + (size_t)r*DK)) + c);
            CP16(sb + 3*TILE_B + d, ((const uint4*)(gwl + (size_t)r*DK)) + c);
        }
        CP_COMMIT();
        CP_WAIT(0);
    }
    __syncthreads();

    uint32_t oa_h[4][4], oa_l[4][4];
    {
        int row = w*16 + (l & 7) + ((l >> 3) & 1)*8;
        int colb_off = ((l >> 3) & 2)*8;
        #pragma unroll
        for (int t = 0; t < 4; t++) {
            uint32_t a = sb + row*RSTRIDE_B + t*32 + colb_off;
            LDSM_X4(oa_h[t][0], oa_h[t][1], oa_h[t][2], oa_h[t][3], a);
            LDSM_X4(oa_l[t][0], oa_l[t][1], oa_l[t][2], oa_l[t][3], a + TILE_B);
        }
    }

    const int brow  = (l & 7) + ((l >> 3) & 2)*4;
    const int bcolb = ((l >> 3) & 1)*16;
    const int row_lo = row0 + w*16 + (l >> 2);
    const int row_hi = row_lo + 8;

    for (int nc = 0; nc < 16; nc++) {
        const int n0 = nc*64;
        if (nc + 1 < 16) {
            uint32_t wb = sb + 2*TILE_B + ((nc+1)&1)*2*TILE_B;
            #pragma unroll
            for (int it = 0; it < 4; it++) {
                int i = tid + it*128;
                int r = i >> 3, c = i & 7;
                uint32_t d = r*RSTRIDE_B + c*16;
                CP16(wb + d,          ((const uint4*)(gwh + (size_t)(n0 + 64 + r)*DK)) + c);
                CP16(wb + TILE_B + d, ((const uint4*)(gwl + (size_t)(n0 + 64 + r)*DK)) + c);
            }
            CP_COMMIT();
            CP_WAIT(1);
        } else {
            CP_WAIT(0);
        }
        __syncthreads();

        const uint32_t aWh = sb + 2*TILE_B + (nc&1)*2*TILE_B;
        float C[8][4];
        #pragma unroll
        for (int j = 0; j < 8; j++)
            #pragma unroll
            for (int i = 0; i < 4; i++) C[j][i] = 0.f;

        #pragma unroll
        for (int t = 0; t < 4; t++) {
            #pragma unroll
            for (int g = 0; g < 4; g++) {
                uint32_t ba = aWh + (g*16 + brow)*RSTRIDE_B + t*32 + bcolb;
                uint32_t h0,h1,h2,h3, w0,w1,w2,w3;
                LDSM_X4(h0,h1,h2,h3, ba);
                LDSM_X4(w0,w1,w2,w3, ba + TILE_B);
                MMA16816(C[2*g],   oa_h[t][0],oa_h[t][1],oa_h[t][2],oa_h[t][3], h0,h1);
                MMA16816(C[2*g],   oa_h[t][0],oa_h[t][1],oa_h[t][2],oa_h[t][3], w0,w1);
                MMA16816(C[2*g],   oa_l[t][0],oa_l[t][1],oa_l[t][2],oa_l[t][3], h0,h1);
                MMA16816(C[2*g+1], oa_h[t][0],oa_h[t][1],oa_h[t][2],oa_h[t][3], h2,h3);
                MMA16816(C[2*g+1], oa_h[t][0],oa_h[t][1],oa_h[t][2],oa_h[t][3], w2,w3);
                MMA16816(C[2*g+1], oa_l[t][0],oa_l[t][1],oa_l[t][2],oa_l[t][3], h2,h3);
            }
        }

        float2* po0 = (float2*)(out + (size_t)row_lo*DM + n0);
        float2* po1 = (float2*)(out + (size_t)row_hi*DM + n0);
        #pragma unroll
        for (int j = 0; j < 8; j++) {
            int c = j*8 + 2*(l & 3);
            float b0v = bo[n0 + c], b1v = bo[n0 + c + 1];
            float2 v0 = { C[j][0] + b0v, C[j][1] + b1v };
            float2 v1 = { C[j][2] + b0v, C[j][3] + b1v };
            po0[j*4 + (l & 3)] = v0;
            po1[j*4 + (l & 3)] = v1;
        }
        __syncthreads();
    }
}

// ---------------------------------------------------------------------------
extern "C" void kernel_launch(void* const* d_in, const int* in_sizes, int n_in,
                              void* d_out, int out_size)
{
    const float* q    = (const float*)d_in[0];
    const float* k    = (const float*)d_in[1];
    const float* v    = (const float*)d_in[2];
    const int*   mask = (const int*)  d_in[3];
    const float* Wq   = (const float*)d_in[4];
    const float* bq   = (const float*)d_in[5];
    const float* Wk   = (const float*)d_in[6];
    const float* bk   = (const float*)d_in[7];
    const float* Wv   = (const float*)d_in[8];
    const float* bv   = (const float*)d_in[9];
    const float* Wo   = (const float*)d_in[10];
    const float* bo   = (const float*)d_in[11];
    float* out = (float*)d_out;

    const int smem6 = 6*TILE_B;    // 55296
    const int smem5 = 5*TILE_B;    // 46080
    cudaFuncSetAttribute(proj_mma_kernel,
                         cudaFuncAttributeMaxDynamicSharedMemorySize, smem6);
    cudaFuncSetAttribute(attn_mma_kernel,
                         cudaFuncAttributeMaxDynamicSharedMemorySize, smem5);
    cudaFuncSetAttribute(oproj_mma_kernel,
                         cudaFuncAttributeMaxDynamicSharedMemorySize, smem6);

    pack_mask_kernel<<<SEQ*SEQ/4/256, 256>>>(mask);
    split_w_kernel<<<dim3(64, 4), 256>>>(Wq, Wk, Wv, Wo);

    proj_mma_kernel<<<dim3(MTOT/64, 3), 128, smem6>>>(q, k, v, bq, bk, bv);

    attn_mma_kernel<<<dim3(SEQ/64, BB, NSPLIT), 128, smem5>>>();

    merge_kernel<<<MTOT/16, 256>>>();

    oproj_mma_kernel<<<MTOT/64, 128, smem6>>>(bo, out);
}